// round 15
// baseline (speedup 1.0000x reference)
#include <cuda_runtime.h>
#include <cuda_fp16.h>

#define NN 100000
#define DD 64
#define HH 4096
#define G3H 12288   // 3*HH
#define EE 3200000
#define SCAN_B 512

// ---------------- scratch (static device globals; no allocation) ----------
__device__ int   g_outc[NN];
__device__ int   g_inc[NN];
__device__ float g_outn[NN];
__device__ float g_inn[NN];
__device__ int   g_rowptr[NN + 1];
__device__ int   g_bsum[256];
__device__ int   g_eloc[EE];                 // per-edge within-row offset
__device__ int   g_csrc[EE];                 // edge src ids sorted by dst
__device__ __half g_yh[(size_t)NN * DD];     // pre-scaled features, fp16
__device__ __half g_h1h[(size_t)NN * DD];    // layer-1 output (outn-scaled), fp16
__device__ float g_gi[2 * G3H];
__device__ float g_gh[2 * G3H];
__device__ float g_w[2 * HH];                // evolved weights w1, w2

// ---------------- zero counts ---------------------------------------------
__global__ void k_zero_cnt(int N) {
    int i = blockIdx.x * blockDim.x + threadIdx.x;
    if (i < N) { g_outc[i] = 0; g_inc[i] = 0; }
}

// ---------------- in-degree histogram + per-edge local offset --------------
__global__ void k_count_in(const int* __restrict__ dst, int E) {
    int stride = gridDim.x * blockDim.x;
    int E4 = E >> 2;
    const int4* d4 = (const int4*)dst;
    for (int i = blockIdx.x * blockDim.x + threadIdx.x; i < E4; i += stride) {
        int4 d = d4[i];
        int4 e;
        e.x = atomicAdd(&g_inc[d.x], 1);
        e.y = atomicAdd(&g_inc[d.y], 1);
        e.z = atomicAdd(&g_inc[d.z], 1);
        e.w = atomicAdd(&g_inc[d.w], 1);
        ((int4*)g_eloc)[i] = e;
    }
    for (int i = (E4 << 2) + blockIdx.x * blockDim.x + threadIdx.x; i < E; i += stride)
        g_eloc[i] = atomicAdd(&g_inc[dst[i]], 1);
}

// ---------------- out-degree histogram (off critical path, s2) -------------
__global__ void k_count_out(const int* __restrict__ src, int E) {
    int stride = gridDim.x * blockDim.x;
    int E4 = E >> 2;
    const int4* s4 = (const int4*)src;
    for (int i = blockIdx.x * blockDim.x + threadIdx.x; i < E4; i += stride) {
        int4 s = s4[i];
        atomicAdd(&g_outc[s.x], 1);
        atomicAdd(&g_outc[s.y], 1);
        atomicAdd(&g_outc[s.z], 1);
        atomicAdd(&g_outc[s.w], 1);
    }
    for (int i = (E4 << 2) + blockIdx.x * blockDim.x + threadIdx.x; i < E; i += stride)
        atomicAdd(&g_outc[src[i]], 1);
}

__global__ void k_norm_out(int N) {
    int i = blockIdx.x * blockDim.x + threadIdx.x;
    if (i < N) g_outn[i] = rsqrtf(fmaxf((float)g_outc[i], 1.0f));
}

// ---------------- exclusive scan of in-counts -> rowptr (+ inn) ------------
__global__ void k_scan1(int N) {
    __shared__ int sh[SCAN_B];
    int tid = threadIdx.x;
    int i = blockIdx.x * SCAN_B + tid;
    int v = (i < N) ? g_inc[i] : 0;
    if (i < N) g_inn[i] = rsqrtf(fmaxf((float)v, 1.0f));
    sh[tid] = v;
    __syncthreads();
#pragma unroll
    for (int o = 1; o < SCAN_B; o <<= 1) {
        int t = (tid >= o) ? sh[tid - o] : 0;
        __syncthreads();
        sh[tid] += t;
        __syncthreads();
    }
    if (i < N) g_rowptr[i] = sh[tid] - v;
    if (tid == SCAN_B - 1) g_bsum[blockIdx.x] = sh[tid];
}

__global__ void k_scan2(int nb) {
    __shared__ int sh[256];
    int tid = threadIdx.x;
    int v = (tid < nb) ? g_bsum[tid] : 0;
    sh[tid] = v;
    __syncthreads();
#pragma unroll
    for (int o = 1; o < 256; o <<= 1) {
        int t = (tid >= o) ? sh[tid - o] : 0;
        __syncthreads();
        sh[tid] += t;
        __syncthreads();
    }
    if (tid < nb) g_bsum[tid] = sh[tid] - v;
}

__global__ void k_scan3(int N, int E) {
    int i = blockIdx.x * blockDim.x + threadIdx.x;
    if (i < N) g_rowptr[i] += g_bsum[i / SCAN_B];
    if (i == 0) g_rowptr[N] = E;
}

// ---------------- scatter edges into CSR (no atomics) ----------------------
__global__ void k_scatter(const int* __restrict__ src, const int* __restrict__ dst, int E) {
    int stride = gridDim.x * blockDim.x;
    int E4 = E >> 2;
    const int4* s4 = (const int4*)src;
    const int4* d4 = (const int4*)dst;
    const int4* e4 = (const int4*)g_eloc;
    for (int i = blockIdx.x * blockDim.x + threadIdx.x; i < E4; i += stride) {
        int4 s = s4[i];
        int4 d = d4[i];
        int4 e = e4[i];
        g_csrc[g_rowptr[d.x] + e.x] = s.x;
        g_csrc[g_rowptr[d.y] + e.y] = s.y;
        g_csrc[g_rowptr[d.z] + e.z] = s.z;
        g_csrc[g_rowptr[d.w] + e.w] = s.w;
    }
    for (int i = (E4 << 2) + blockIdx.x * blockDim.x + threadIdx.x; i < E; i += stride)
        g_csrc[g_rowptr[dst[i]] + g_eloc[i]] = src[i];
}

// ---------------- batched GEMV for GRU gates (side stream) -----------------
__global__ __launch_bounds__(256) void k_gemv(
    const float* __restrict__ W_ih, const float* __restrict__ W_hh,
    const float* __restrict__ xi0, const float* __restrict__ xi1,
    const float* __restrict__ xh0, const float* __restrict__ xh1,
    const float* __restrict__ b_ih, const float* __restrict__ b_hh)
{
    __shared__ float4 xs0[HH / 4];
    __shared__ float4 xs1[HH / 4];

    int nb = gridDim.x >> 1;
    int m  = (blockIdx.x >= nb) ? 1 : 0;
    int bb = blockIdx.x - m * nb;

    const float* W    = m ? W_hh : W_ih;
    const float* xa   = m ? xh0 : xi0;
    const float* xb   = m ? xh1 : xi1;
    const float* bias = m ? b_hh : b_ih;
    float* out        = m ? g_gh : g_gi;

    const float4* xa4 = (const float4*)xa;
    const float4* xb4 = (const float4*)xb;
    for (int i = threadIdx.x; i < HH / 4; i += blockDim.x) {
        xs0[i] = xa4[i];
        xs1[i] = xb4[i];
    }
    __syncthreads();

    int warp = threadIdx.x >> 5;
    int lane = threadIdx.x & 31;
    int r = bb * 8 + warp;
    if (r >= G3H) return;

    const float4* Wr = (const float4*)(W + (size_t)r * HH);
    float a0 = 0.f, a1 = 0.f;
#pragma unroll 8
    for (int i = 0; i < 32; i++) {
        float4 w = Wr[i * 32 + lane];
        float4 p = xs0[i * 32 + lane];
        float4 q = xs1[i * 32 + lane];
        a0 += w.x * p.x + w.y * p.y + w.z * p.z + w.w * p.w;
        a1 += w.x * q.x + w.y * q.y + w.z * q.z + w.w * q.w;
    }
#pragma unroll
    for (int o = 16; o; o >>= 1) {
        a0 += __shfl_xor_sync(0xffffffffu, a0, o);
        a1 += __shfl_xor_sync(0xffffffffu, a1, o);
    }
    if (lane == 0) {
        float bv = bias[r];
        out[r]       = a0 + bv;
        out[G3H + r] = a1 + bv;
    }
}

// ---------------- GRU elementwise ------------------------------------------
__global__ void k_gru(const float* __restrict__ gc1w, const float* __restrict__ gc2w) {
    int idx = blockIdx.x * blockDim.x + threadIdx.x;
    if (idx >= 2 * HH) return;
    int b = idx >> 12;
    int i = idx & (HH - 1);
    const float* gi = g_gi + b * G3H;
    const float* gh = g_gh + b * G3H;
    float hcur = (b ? gc2w : gc1w)[i];
    float r = 1.0f / (1.0f + expf(-(gi[i] + gh[i])));
    float z = 1.0f / (1.0f + expf(-(gi[HH + i] + gh[HH + i])));
    float n = tanhf(gi[2 * HH + i] + r * gh[2 * HH + i]);
    g_w[b * HH + i] = (1.0f - z) * n + z * hcur;
}

// ---------------- feature pre-scale -> fp16 --------------------------------
__global__ void k_prescale(const float* __restrict__ x, int N) {
    int i = blockIdx.x * blockDim.x + threadIdx.x;
    int n4 = N * (DD / 4);
    if (i < n4) {
        float s = g_outn[i >> 4];
        float4 v = ((const float4*)x)[i];
        __half2 a = __floats2half2_rn(v.x * s, v.y * s);
        __half2 b = __floats2half2_rn(v.z * s, v.w * s);
        uint2 pv;
        pv.x = *reinterpret_cast<unsigned*>(&a);
        pv.y = *reinterpret_cast<unsigned*>(&b);
        ((uint2*)g_yh)[i] = pv;
    }
}

// ---------------- fused layer: CSR pull (fp16, LDG.128, 4 edges/step) ------
// (byte-identical to round-13 best)
__global__ __launch_bounds__(256) void k_layer(
    const __half* __restrict__ y, float* __restrict__ outf,
    const float* __restrict__ bias, int which, int mode, int N)
{
    __shared__ float Ws[DD * DD];
    __shared__ float bs[DD];
    __shared__ float sh_agg[8 * DD];
    __shared__ int   sh_idx[8 * 32];

    const float* Wd = g_w + which * HH;
    for (int i = threadIdx.x; i < DD * DD; i += blockDim.x) Ws[i] = Wd[i];
    if (threadIdx.x < DD) bs[threadIdx.x] = bias[threadIdx.x];
    __syncthreads();

    const unsigned FULL = 0xffffffffu;
    int lane = threadIdx.x & 31;
    int wid  = threadIdx.x >> 5;
    int esel = lane >> 3;                    // which of 4 edges this lane serves
    int c    = lane & 7;                     // 16B chunk (8 halves) within 128B row
    const uint4* y4 = (const uint4*)y;
    float4* sh4 = (float4*)(sh_agg + wid * DD + c * 8);
    int* sidx = sh_idx + wid * 32;

    int gw = (blockIdx.x * blockDim.x + threadIdx.x) >> 5;
    int tw = (gridDim.x * blockDim.x) >> 5;

    for (int row = gw; row < N; row += tw) {
        int beg = g_rowptr[row];
        int end = g_rowptr[row + 1];

        float4 aA0 = make_float4(0.f,0.f,0.f,0.f), aB0 = make_float4(0.f,0.f,0.f,0.f);
        float4 aA1 = make_float4(0.f,0.f,0.f,0.f), aB1 = make_float4(0.f,0.f,0.f,0.f);

        for (int base = beg; base < end; base += 32) {
            int m = min(32, end - base);
            if (m == 32) {
                sidx[lane] = g_csrc[base + lane];
                __syncwarp();
#pragma unroll
                for (int j = 0; j < 8; j++) {
                    int se = sidx[(j << 2) + esel];
                    uint4 v = y4[(size_t)se * 8 + c];
                    __half2 h0 = *reinterpret_cast<__half2*>(&v.x);
                    __half2 h1 = *reinterpret_cast<__half2*>(&v.y);
                    __half2 h2 = *reinterpret_cast<__half2*>(&v.z);
                    __half2 h3 = *reinterpret_cast<__half2*>(&v.w);
                    float2 f0 = __half22float2(h0);
                    float2 f1 = __half22float2(h1);
                    float2 f2 = __half22float2(h2);
                    float2 f3 = __half22float2(h3);
                    if (j & 1) {
                        aA1.x += f0.x; aA1.y += f0.y; aA1.z += f1.x; aA1.w += f1.y;
                        aB1.x += f2.x; aB1.y += f2.y; aB1.z += f3.x; aB1.w += f3.y;
                    } else {
                        aA0.x += f0.x; aA0.y += f0.y; aA0.z += f1.x; aA0.w += f1.y;
                        aB0.x += f2.x; aB0.y += f2.y; aB0.z += f3.x; aB0.w += f3.y;
                    }
                }
                __syncwarp();
            } else {
                int s = 0;
                if (lane < m) s = g_csrc[base + lane];
#pragma unroll 8
                for (int j = 0; j < 32; j += 4) {
                    if (j >= m) break;
                    int e = j + esel;
                    int se = __shfl_sync(FULL, s, e);
                    if (e < m) {
                        uint4 v = y4[(size_t)se * 8 + c];
                        __half2 h0 = *reinterpret_cast<__half2*>(&v.x);
                        __half2 h1 = *reinterpret_cast<__half2*>(&v.y);
                        __half2 h2 = *reinterpret_cast<__half2*>(&v.z);
                        __half2 h3 = *reinterpret_cast<__half2*>(&v.w);
                        float2 f0 = __half22float2(h0);
                        float2 f1 = __half22float2(h1);
                        float2 f2 = __half22float2(h2);
                        float2 f3 = __half22float2(h3);
                        if (j & 4) {
                            aA1.x += f0.x; aA1.y += f0.y; aA1.z += f1.x; aA1.w += f1.y;
                            aB1.x += f2.x; aB1.y += f2.y; aB1.z += f3.x; aB1.w += f3.y;
                        } else {
                            aA0.x += f0.x; aA0.y += f0.y; aA0.z += f1.x; aA0.w += f1.y;
                            aB0.x += f2.x; aB0.y += f2.y; aB0.z += f3.x; aB0.w += f3.y;
                        }
                    }
                }
            }
        }
        aA0.x += aA1.x; aA0.y += aA1.y; aA0.z += aA1.z; aA0.w += aA1.w;
        aB0.x += aB1.x; aB0.y += aB1.y; aB0.z += aB1.z; aB0.w += aB1.w;

#pragma unroll
        for (int o = 8; o <= 16; o <<= 1) {
            aA0.x += __shfl_xor_sync(FULL, aA0.x, o);
            aA0.y += __shfl_xor_sync(FULL, aA0.y, o);
            aA0.z += __shfl_xor_sync(FULL, aA0.z, o);
            aA0.w += __shfl_xor_sync(FULL, aA0.w, o);
            aB0.x += __shfl_xor_sync(FULL, aB0.x, o);
            aB0.y += __shfl_xor_sync(FULL, aB0.y, o);
            aB0.z += __shfl_xor_sync(FULL, aB0.z, o);
            aB0.w += __shfl_xor_sync(FULL, aB0.w, o);
        }
        __syncwarp();
        if (esel == 0) { sh4[0] = aA0; sh4[1] = aB0; }
        __syncwarp();

        float inn = g_inn[row];
        float a0 = sh_agg[wid * DD + lane] * inn;
        float a1 = sh_agg[wid * DD + lane + 32] * inn;
        __syncwarp();

        float r0 = bs[lane], r1 = bs[lane + 32];
#pragma unroll
        for (int k = 0; k < 32; k++) {
            float ak = __shfl_sync(FULL, a0, k);
            r0 += ak * Ws[k * 64 + lane];
            r1 += ak * Ws[k * 64 + lane + 32];
        }
#pragma unroll
        for (int k = 0; k < 32; k++) {
            float ak = __shfl_sync(FULL, a1, k);
            r0 += ak * Ws[(k + 32) * 64 + lane];
            r1 += ak * Ws[(k + 32) * 64 + lane + 32];
        }
        if (mode == 0) {
            float on = g_outn[row];
            g_h1h[(size_t)row * DD + lane]      = __float2half_rn(fmaxf(r0, 0.f) * on);
            g_h1h[(size_t)row * DD + lane + 32] = __float2half_rn(fmaxf(r1, 0.f) * on);
        } else {
            outf[(size_t)row * DD + lane]      = r0;
            outf[(size_t)row * DD + lane + 32] = r1;
        }
    }
}

// ---------------- launch ----------------------------------------------------
extern "C" void kernel_launch(void* const* d_in, const int* in_sizes, int n_in,
                              void* d_out, int out_size)
{
    const float* node  = (const float*)d_in[0];
    const float* gc1w  = (const float*)d_in[1];
    const float* gc2w  = (const float*)d_in[2];
    const float* gc1b  = (const float*)d_in[3];
    const float* gc2b  = (const float*)d_in[4];
    const float* prev1 = (const float*)d_in[5];
    const float* prev2 = (const float*)d_in[6];
    const float* Wih   = (const float*)d_in[7];
    const float* Whh   = (const float*)d_in[8];
    const float* bih   = (const float*)d_in[9];
    const float* bhh   = (const float*)d_in[10];
    const int*   src   = (const int*)d_in[11];
    const int*   dst   = (const int*)d_in[12];
    float* out = (float*)d_out;

    int N = in_sizes[0] / DD;
    int E = in_sizes[11];
    int nbScan = (N + SCAN_B - 1) / SCAN_B;

    static cudaStream_t s1 = nullptr, s2 = nullptr;
    static cudaEvent_t ev0 = nullptr, ev1 = nullptr, evC = nullptr, evP = nullptr;
    if (!s1) {
        cudaStreamCreateWithFlags(&s1, cudaStreamNonBlocking);
        cudaStreamCreateWithFlags(&s2, cudaStreamNonBlocking);
        cudaEventCreateWithFlags(&ev0, cudaEventDisableTiming);
        cudaEventCreateWithFlags(&ev1, cudaEventDisableTiming);
        cudaEventCreateWithFlags(&evC, cudaEventDisableTiming);
        cudaEventCreateWithFlags(&evP, cudaEventDisableTiming);
    }

    // fork: GRU weight evolution on side stream (DRAM-bound, overlaps build)
    cudaEventRecord(ev0, 0);
    cudaStreamWaitEvent(s1, ev0, 0);
    k_gemv<<<2 * (G3H / 8), 256, 0, s1>>>(Wih, Whh, prev1, prev2, gc1w, gc2w, bih, bhh);
    k_gru<<<(2 * HH + 255) / 256, 256, 0, s1>>>(gc1w, gc2w);
    cudaEventRecord(ev1, s1);

    // s0 critical path: zero -> in-histogram -> scans(+inn) -> scatter
    k_zero_cnt<<<(N + 255) / 256, 256>>>(N);
    k_count_in<<<2048, 256>>>(dst, E);
    cudaEventRecord(evC, 0);

    // fork to s2: out-histogram -> outn -> prescale (overlaps scans+scatter)
    cudaStreamWaitEvent(s2, evC, 0);
    k_count_out<<<2048, 256, 0, s2>>>(src, E);
    k_norm_out<<<(N + 255) / 256, 256, 0, s2>>>(N);
    k_prescale<<<(N * 16 + 255) / 256, 256, 0, s2>>>(node, N);
    cudaEventRecord(evP, s2);

    k_scan1<<<nbScan, SCAN_B>>>(N);
    k_scan2<<<1, 256>>>(nbScan);
    k_scan3<<<(N + 255) / 256, 256>>>(N, E);
    k_scatter<<<2048, 256>>>(src, dst, E);

    // join: layers need evolved weights + CSR + prescaled features + norms
    cudaStreamWaitEvent(0, ev1, 0);
    cudaStreamWaitEvent(0, evP, 0);

    __half* yh = nullptr; __half* h1h = nullptr;
    cudaGetSymbolAddress((void**)&yh, g_yh);
    cudaGetSymbolAddress((void**)&h1h, g_h1h);
    k_layer<<<2048, 256>>>(yh, out, gc1b, 0, 0, N);
    k_layer<<<2048, 256>>>(h1h, out, gc2b, 1, 1, N);
}

// round 16
// speedup vs baseline: 1.0197x; 1.0197x over previous
#include <cuda_runtime.h>
#include <cuda_fp16.h>

#define NN 100000
#define DD 64
#define HH 4096
#define G3H 12288   // 3*HH
#define EE 3200000
#define SCAN_B 512

// ---------------- scratch (static device globals; no allocation) ----------
__device__ int   g_outc[NN];
__device__ int   g_inc[NN];
__device__ float g_outn[NN];
__device__ float g_inn[NN];
__device__ int   g_rowptr[NN + 1];
__device__ int   g_bsum[256];
__device__ int   g_eloc[EE];                 // per-edge within-row offset
__device__ int   g_csrc[EE];                 // edge src ids sorted by dst
__device__ __half g_yh[(size_t)NN * DD];     // pre-scaled features, fp16
__device__ __half g_h1h[(size_t)NN * DD];    // layer-1 output (outn-scaled), fp16
__device__ float g_gi[2 * G3H];
__device__ float g_gh[2 * G3H];
__device__ float g_w[2 * HH];                // evolved weights w1, w2

// ---------------- zero counts ---------------------------------------------
__global__ void k_zero_cnt(int N) {
    int i = blockIdx.x * blockDim.x + threadIdx.x;
    if (i < N) { g_outc[i] = 0; g_inc[i] = 0; }
}

// ---------------- degree histogram + per-edge local offset -----------------
__global__ void k_count(const int* __restrict__ src, const int* __restrict__ dst, int E) {
    int stride = gridDim.x * blockDim.x;
    int E4 = E >> 2;
    const int4* s4 = (const int4*)src;
    const int4* d4 = (const int4*)dst;
    for (int i = blockIdx.x * blockDim.x + threadIdx.x; i < E4; i += stride) {
        int4 s = s4[i];
        int4 d = d4[i];
        atomicAdd(&g_outc[s.x], 1);
        atomicAdd(&g_outc[s.y], 1);
        atomicAdd(&g_outc[s.z], 1);
        atomicAdd(&g_outc[s.w], 1);
        int4 e;
        e.x = atomicAdd(&g_inc[d.x], 1);
        e.y = atomicAdd(&g_inc[d.y], 1);
        e.z = atomicAdd(&g_inc[d.z], 1);
        e.w = atomicAdd(&g_inc[d.w], 1);
        ((int4*)g_eloc)[i] = e;
    }
    for (int i = (E4 << 2) + blockIdx.x * blockDim.x + threadIdx.x; i < E; i += stride) {
        atomicAdd(&g_outc[src[i]], 1);
        g_eloc[i] = atomicAdd(&g_inc[dst[i]], 1);
    }
}

__global__ void k_norm(int N) {
    int i = blockIdx.x * blockDim.x + threadIdx.x;
    if (i < N) {
        g_outn[i] = rsqrtf(fmaxf((float)g_outc[i], 1.0f));
        g_inn[i]  = rsqrtf(fmaxf((float)g_inc[i], 1.0f));
    }
}

// ---------------- exclusive scan of in-counts -> rowptr --------------------
__global__ void k_scan1(int N) {
    __shared__ int sh[SCAN_B];
    int tid = threadIdx.x;
    int i = blockIdx.x * SCAN_B + tid;
    int v = (i < N) ? g_inc[i] : 0;
    sh[tid] = v;
    __syncthreads();
#pragma unroll
    for (int o = 1; o < SCAN_B; o <<= 1) {
        int t = (tid >= o) ? sh[tid - o] : 0;
        __syncthreads();
        sh[tid] += t;
        __syncthreads();
    }
    if (i < N) g_rowptr[i] = sh[tid] - v;
    if (tid == SCAN_B - 1) g_bsum[blockIdx.x] = sh[tid];
}

__global__ void k_scan2(int nb) {
    __shared__ int sh[256];
    int tid = threadIdx.x;
    int v = (tid < nb) ? g_bsum[tid] : 0;
    sh[tid] = v;
    __syncthreads();
#pragma unroll
    for (int o = 1; o < 256; o <<= 1) {
        int t = (tid >= o) ? sh[tid - o] : 0;
        __syncthreads();
        sh[tid] += t;
        __syncthreads();
    }
    if (tid < nb) g_bsum[tid] = sh[tid] - v;
}

__global__ void k_scan3(int N, int E) {
    int i = blockIdx.x * blockDim.x + threadIdx.x;
    if (i < N) g_rowptr[i] += g_bsum[i / SCAN_B];
    if (i == 0) g_rowptr[N] = E;
}

// ---------------- scatter edges into CSR (no atomics) ----------------------
__global__ void k_scatter(const int* __restrict__ src, const int* __restrict__ dst, int E) {
    int stride = gridDim.x * blockDim.x;
    int E4 = E >> 2;
    const int4* s4 = (const int4*)src;
    const int4* d4 = (const int4*)dst;
    const int4* e4 = (const int4*)g_eloc;
    for (int i = blockIdx.x * blockDim.x + threadIdx.x; i < E4; i += stride) {
        int4 s = s4[i];
        int4 d = d4[i];
        int4 e = e4[i];
        g_csrc[g_rowptr[d.x] + e.x] = s.x;
        g_csrc[g_rowptr[d.y] + e.y] = s.y;
        g_csrc[g_rowptr[d.z] + e.z] = s.z;
        g_csrc[g_rowptr[d.w] + e.w] = s.w;
    }
    for (int i = (E4 << 2) + blockIdx.x * blockDim.x + threadIdx.x; i < E; i += stride)
        g_csrc[g_rowptr[dst[i]] + g_eloc[i]] = src[i];
}

// ---------------- batched GEMV for GRU gates (side stream) -----------------
__global__ __launch_bounds__(256) void k_gemv(
    const float* __restrict__ W_ih, const float* __restrict__ W_hh,
    const float* __restrict__ xi0, const float* __restrict__ xi1,
    const float* __restrict__ xh0, const float* __restrict__ xh1,
    const float* __restrict__ b_ih, const float* __restrict__ b_hh)
{
    __shared__ float4 xs0[HH / 4];
    __shared__ float4 xs1[HH / 4];

    int nb = gridDim.x >> 1;
    int m  = (blockIdx.x >= nb) ? 1 : 0;
    int bb = blockIdx.x - m * nb;

    const float* W    = m ? W_hh : W_ih;
    const float* xa   = m ? xh0 : xi0;
    const float* xb   = m ? xh1 : xi1;
    const float* bias = m ? b_hh : b_ih;
    float* out        = m ? g_gh : g_gi;

    const float4* xa4 = (const float4*)xa;
    const float4* xb4 = (const float4*)xb;
    for (int i = threadIdx.x; i < HH / 4; i += blockDim.x) {
        xs0[i] = xa4[i];
        xs1[i] = xb4[i];
    }
    __syncthreads();

    int warp = threadIdx.x >> 5;
    int lane = threadIdx.x & 31;
    int r = bb * 8 + warp;
    if (r >= G3H) return;

    const float4* Wr = (const float4*)(W + (size_t)r * HH);
    float a0 = 0.f, a1 = 0.f;
#pragma unroll 8
    for (int i = 0; i < 32; i++) {
        float4 w = Wr[i * 32 + lane];
        float4 p = xs0[i * 32 + lane];
        float4 q = xs1[i * 32 + lane];
        a0 += w.x * p.x + w.y * p.y + w.z * p.z + w.w * p.w;
        a1 += w.x * q.x + w.y * q.y + w.z * q.z + w.w * q.w;
    }
#pragma unroll
    for (int o = 16; o; o >>= 1) {
        a0 += __shfl_xor_sync(0xffffffffu, a0, o);
        a1 += __shfl_xor_sync(0xffffffffu, a1, o);
    }
    if (lane == 0) {
        float bv = bias[r];
        out[r]       = a0 + bv;
        out[G3H + r] = a1 + bv;
    }
}

// ---------------- GRU elementwise ------------------------------------------
__global__ void k_gru(const float* __restrict__ gc1w, const float* __restrict__ gc2w) {
    int idx = blockIdx.x * blockDim.x + threadIdx.x;
    if (idx >= 2 * HH) return;
    int b = idx >> 12;
    int i = idx & (HH - 1);
    const float* gi = g_gi + b * G3H;
    const float* gh = g_gh + b * G3H;
    float hcur = (b ? gc2w : gc1w)[i];
    float r = 1.0f / (1.0f + expf(-(gi[i] + gh[i])));
    float z = 1.0f / (1.0f + expf(-(gi[HH + i] + gh[HH + i])));
    float n = tanhf(gi[2 * HH + i] + r * gh[2 * HH + i]);
    g_w[b * HH + i] = (1.0f - z) * n + z * hcur;
}

// ---------------- feature pre-scale -> fp16 --------------------------------
__global__ void k_prescale(const float* __restrict__ x, int N) {
    int i = blockIdx.x * blockDim.x + threadIdx.x;
    int n4 = N * (DD / 4);
    if (i < n4) {
        float s = g_outn[i >> 4];
        float4 v = ((const float4*)x)[i];
        __half2 a = __floats2half2_rn(v.x * s, v.y * s);
        __half2 b = __floats2half2_rn(v.z * s, v.w * s);
        uint2 pv;
        pv.x = *reinterpret_cast<unsigned*>(&a);
        pv.y = *reinterpret_cast<unsigned*>(&b);
        ((uint2*)g_yh)[i] = pv;
    }
}

// ---------------- fused layer: CSR pull (fp16, LDG.128, 4 edges/step) ------
// agg[row] = sum_{s in nbr(row)} y[s]   (y already outn-scaled; fp32 accum)
// t = inn[row]*(agg @ W) + b
// mode 0: h1h[row] = fp16( outn[row] * relu(t) )
// mode 1: out[row] = t (fp32)
// 8 accumulator regs (single chain set) + min-6-blocks bound -> higher occupancy
__global__ __launch_bounds__(256, 6) void k_layer(
    const __half* __restrict__ y, float* __restrict__ outf,
    const float* __restrict__ bias, int which, int mode, int N)
{
    __shared__ float Ws[DD * DD];
    __shared__ float bs[DD];
    __shared__ float sh_agg[8 * DD];
    __shared__ int   sh_idx[8 * 32];

    const float* Wd = g_w + which * HH;
    for (int i = threadIdx.x; i < DD * DD; i += blockDim.x) Ws[i] = Wd[i];
    if (threadIdx.x < DD) bs[threadIdx.x] = bias[threadIdx.x];
    __syncthreads();

    const unsigned FULL = 0xffffffffu;
    int lane = threadIdx.x & 31;
    int wid  = threadIdx.x >> 5;
    int esel = lane >> 3;                    // which of 4 edges this lane serves
    int c    = lane & 7;                     // 16B chunk (8 halves) within 128B row
    const uint4* y4 = (const uint4*)y;
    float4* sh4 = (float4*)(sh_agg + wid * DD + c * 8);
    int* sidx = sh_idx + wid * 32;

    int gw = (blockIdx.x * blockDim.x + threadIdx.x) >> 5;
    int tw = (gridDim.x * blockDim.x) >> 5;

    for (int row = gw; row < N; row += tw) {
        int beg = g_rowptr[row];
        int end = g_rowptr[row + 1];

        float4 aA0 = make_float4(0.f,0.f,0.f,0.f), aB0 = make_float4(0.f,0.f,0.f,0.f);

        for (int base = beg; base < end; base += 32) {
            int m = min(32, end - base);
            if (m == 32) {
                sidx[lane] = g_csrc[base + lane];
                __syncwarp();
#pragma unroll
                for (int j = 0; j < 8; j++) {
                    int se = sidx[(j << 2) + esel];
                    uint4 v = y4[(size_t)se * 8 + c];
                    __half2 h0 = *reinterpret_cast<__half2*>(&v.x);
                    __half2 h1 = *reinterpret_cast<__half2*>(&v.y);
                    __half2 h2 = *reinterpret_cast<__half2*>(&v.z);
                    __half2 h3 = *reinterpret_cast<__half2*>(&v.w);
                    float2 f0 = __half22float2(h0);
                    float2 f1 = __half22float2(h1);
                    float2 f2 = __half22float2(h2);
                    float2 f3 = __half22float2(h3);
                    aA0.x += f0.x; aA0.y += f0.y; aA0.z += f1.x; aA0.w += f1.y;
                    aB0.x += f2.x; aB0.y += f2.y; aB0.z += f3.x; aB0.w += f3.y;
                }
                __syncwarp();
            } else {
                int s = 0;
                if (lane < m) s = g_csrc[base + lane];
#pragma unroll 8
                for (int j = 0; j < 32; j += 4) {
                    if (j >= m) break;
                    int e = j + esel;
                    int se = __shfl_sync(FULL, s, e);
                    if (e < m) {
                        uint4 v = y4[(size_t)se * 8 + c];
                        __half2 h0 = *reinterpret_cast<__half2*>(&v.x);
                        __half2 h1 = *reinterpret_cast<__half2*>(&v.y);
                        __half2 h2 = *reinterpret_cast<__half2*>(&v.z);
                        __half2 h3 = *reinterpret_cast<__half2*>(&v.w);
                        float2 f0 = __half22float2(h0);
                        float2 f1 = __half22float2(h1);
                        float2 f2 = __half22float2(h2);
                        float2 f3 = __half22float2(h3);
                        aA0.x += f0.x; aA0.y += f0.y; aA0.z += f1.x; aA0.w += f1.y;
                        aB0.x += f2.x; aB0.y += f2.y; aB0.z += f3.x; aB0.w += f3.y;
                    }
                }
            }
        }

        // reduce across the 4 edge-groups (xor 8, 16)
#pragma unroll
        for (int o = 8; o <= 16; o <<= 1) {
            aA0.x += __shfl_xor_sync(FULL, aA0.x, o);
            aA0.y += __shfl_xor_sync(FULL, aA0.y, o);
            aA0.z += __shfl_xor_sync(FULL, aA0.z, o);
            aA0.w += __shfl_xor_sync(FULL, aA0.w, o);
            aB0.x += __shfl_xor_sync(FULL, aB0.x, o);
            aB0.y += __shfl_xor_sync(FULL, aB0.y, o);
            aB0.z += __shfl_xor_sync(FULL, aB0.z, o);
            aB0.w += __shfl_xor_sync(FULL, aB0.w, o);
        }
        __syncwarp();
        if (esel == 0) { sh4[0] = aA0; sh4[1] = aB0; }
        __syncwarp();

        float inn = g_inn[row];
        float a0 = sh_agg[wid * DD + lane] * inn;
        float a1 = sh_agg[wid * DD + lane + 32] * inn;
        __syncwarp();

        float r0 = bs[lane], r1 = bs[lane + 32];
#pragma unroll
        for (int k = 0; k < 32; k++) {
            float ak = __shfl_sync(FULL, a0, k);
            r0 += ak * Ws[k * 64 + lane];
            r1 += ak * Ws[k * 64 + lane + 32];
        }
#pragma unroll
        for (int k = 0; k < 32; k++) {
            float ak = __shfl_sync(FULL, a1, k);
            r0 += ak * Ws[(k + 32) * 64 + lane];
            r1 += ak * Ws[(k + 32) * 64 + lane + 32];
        }
        if (mode == 0) {
            float on = g_outn[row];
            g_h1h[(size_t)row * DD + lane]      = __float2half_rn(fmaxf(r0, 0.f) * on);
            g_h1h[(size_t)row * DD + lane + 32] = __float2half_rn(fmaxf(r1, 0.f) * on);
        } else {
            outf[(size_t)row * DD + lane]      = r0;
            outf[(size_t)row * DD + lane + 32] = r1;
        }
    }
}

// ---------------- launch ----------------------------------------------------
extern "C" void kernel_launch(void* const* d_in, const int* in_sizes, int n_in,
                              void* d_out, int out_size)
{
    const float* node  = (const float*)d_in[0];
    const float* gc1w  = (const float*)d_in[1];
    const float* gc2w  = (const float*)d_in[2];
    const float* gc1b  = (const float*)d_in[3];
    const float* gc2b  = (const float*)d_in[4];
    const float* prev1 = (const float*)d_in[5];
    const float* prev2 = (const float*)d_in[6];
    const float* Wih   = (const float*)d_in[7];
    const float* Whh   = (const float*)d_in[8];
    const float* bih   = (const float*)d_in[9];
    const float* bhh   = (const float*)d_in[10];
    const int*   src   = (const int*)d_in[11];
    const int*   dst   = (const int*)d_in[12];
    float* out = (float*)d_out;

    int N = in_sizes[0] / DD;
    int E = in_sizes[11];
    int nbScan = (N + SCAN_B - 1) / SCAN_B;

    static cudaStream_t s1 = nullptr, s2 = nullptr;
    static cudaEvent_t ev0 = nullptr, ev1 = nullptr, evC = nullptr, evP = nullptr;
    if (!s1) {
        cudaStreamCreateWithFlags(&s1, cudaStreamNonBlocking);
        cudaStreamCreateWithFlags(&s2, cudaStreamNonBlocking);
        cudaEventCreateWithFlags(&ev0, cudaEventDisableTiming);
        cudaEventCreateWithFlags(&ev1, cudaEventDisableTiming);
        cudaEventCreateWithFlags(&evC, cudaEventDisableTiming);
        cudaEventCreateWithFlags(&evP, cudaEventDisableTiming);
    }

    // fork: GRU weight evolution on side stream (DRAM-bound, overlaps build)
    cudaEventRecord(ev0, 0);
    cudaStreamWaitEvent(s1, ev0, 0);
    k_gemv<<<2 * (G3H / 8), 256, 0, s1>>>(Wih, Whh, prev1, prev2, gc1w, gc2w, bih, bhh);
    k_gru<<<(2 * HH + 255) / 256, 256, 0, s1>>>(gc1w, gc2w);
    cudaEventRecord(ev1, s1);

    // s0 critical path: zero -> count -> scans -> scatter
    k_zero_cnt<<<(N + 255) / 256, 256>>>(N);
    k_count<<<2048, 256>>>(src, dst, E);
    cudaEventRecord(evC, 0);

    // fork to s2: norm + prescale (depend only on count; overlap scans+scatter)
    cudaStreamWaitEvent(s2, evC, 0);
    k_norm<<<(N + 255) / 256, 256, 0, s2>>>(N);
    k_prescale<<<(N * 16 + 255) / 256, 256, 0, s2>>>(node, N);
    cudaEventRecord(evP, s2);

    k_scan1<<<nbScan, SCAN_B>>>(N);
    k_scan2<<<1, 256>>>(nbScan);
    k_scan3<<<(N + 255) / 256, 256>>>(N, E);
    k_scatter<<<2048, 256>>>(src, dst, E);

    // join: layers need evolved weights + CSR + prescaled features + norms
    cudaStreamWaitEvent(0, ev1, 0);
    cudaStreamWaitEvent(0, evP, 0);

    __half* yh = nullptr; __half* h1h = nullptr;
    cudaGetSymbolAddress((void**)&yh, g_yh);
    cudaGetSymbolAddress((void**)&h1h, g_h1h);
    k_layer<<<2048, 256>>>(yh, out, gc1b, 0, 0, N);
    k_layer<<<2048, 256>>>(h1h, out, gc2b, 1, 1, N);
}